// round 1
// baseline (speedup 1.0000x reference)
#include <cuda_runtime.h>
#include <math.h>

// Problem constants
#define BSZ   4
#define CCH   128
#define NPT   2000
#define KNNK  9
#define NHEAD 4
#define HD    32
#define BN_EPS 1e-5f

// ---------------- scratch (device globals; no allocation allowed) ------------
__device__ float g_w1s[CCH*CCH];
__device__ float g_w1b[CCH*CCH];
// scores buffer: B*H*N*N floats. First B*N*N region doubles as the Gram matrix.
__device__ float g_scores[(size_t)BSZ*NHEAD*NPT*NPT];
__device__ float g_xx[BSZ*NPT];
__device__ int   g_idx[BSZ*NPT*KNNK];
__device__ float g_u[BSZ*CCH*NPT];
__device__ float g_v[BSZ*CCH*NPT];
__device__ float g_h [(size_t)BSZ*CCH*NPT*KNNK];
__device__ float g_h2[(size_t)BSZ*CCH*NPT*KNNK];
__device__ float g_agg[BSZ*CCH*NPT];
__device__ float g_q[BSZ*CCH*NPT];
__device__ float g_k[BSZ*CCH*NPT];
__device__ float g_vv[BSZ*CCH*NPT];
__device__ float g_add[BSZ*CCH*NPT];
__device__ float g_cat[BSZ*2*CCH*NPT];
__device__ float g_hc [BSZ*2*CCH*NPT];

// ---------------- generic tiled SGEMM ---------------------------------------
// C[m,n] = alpha * sum_k Aval(m,k)*Bval(k,n)  (+ epilogue)
// TA: A stored K-major (A[k*lda+m]) else A[m*lda+k]
// TB: B stored N-major (B[n*ldb+k]) else B[k*ldb+n]
#define TM 128
#define TN 128
#define TK 8

template<bool TA, bool TB>
__global__ void __launch_bounds__(256) gemm_k(
    const float* __restrict__ A, const float* __restrict__ B, float* __restrict__ Cm,
    int M, int Nc, int Kc, int lda, int ldb, int ldc,
    long long sA, long long sB, long long sC,
    float alpha,
    const float* __restrict__ bias,
    const float* __restrict__ gamma, const float* __restrict__ beta,
    int relu,
    const float* __restrict__ resid, long long sR, int ldr)
{
    int bz = blockIdx.z;
    A  += (long long)bz * sA;
    B  += (long long)bz * sB;
    Cm += (long long)bz * sC;
    if (resid) resid += (long long)bz * sR;

    __shared__ float As[TK][TM];
    __shared__ float Bs[TK][TN];

    int m0 = blockIdx.y * TM;
    int n0 = blockIdx.x * TN;
    int tid = threadIdx.x;
    int tx = tid % 16, ty = tid / 16;

    float acc[8][8];
    #pragma unroll
    for (int i=0;i<8;i++)
        #pragma unroll
        for (int j=0;j<8;j++) acc[i][j] = 0.f;

    for (int kt = 0; kt < Kc; kt += TK) {
        #pragma unroll
        for (int e = tid; e < TM*TK; e += 256) {
            int m, k;
            if (TA) { m = e % TM; k = e / TM; }
            else    { k = e % TK; m = e / TK; }
            int gm = m0 + m, gk = kt + k;
            float val = 0.f;
            if (gm < M && gk < Kc)
                val = TA ? A[(long long)gk*lda + gm] : A[(long long)gm*lda + gk];
            As[k][m] = val;
        }
        #pragma unroll
        for (int e = tid; e < TN*TK; e += 256) {
            int n, k;
            if (TB) { k = e % TK; n = e / TK; }
            else    { n = e % TN; k = e / TN; }
            int gn = n0 + n, gk = kt + k;
            float val = 0.f;
            if (gn < Nc && gk < Kc)
                val = TB ? B[(long long)gn*ldb + gk] : B[(long long)gk*ldb + gn];
            Bs[k][n] = val;
        }
        __syncthreads();
        #pragma unroll
        for (int kk = 0; kk < TK; kk++) {
            float a[8], b[8];
            #pragma unroll
            for (int i=0;i<8;i++) a[i] = As[kk][ty*8+i];
            #pragma unroll
            for (int j=0;j<8;j++) b[j] = Bs[kk][tx*8+j];
            #pragma unroll
            for (int i=0;i<8;i++)
                #pragma unroll
                for (int j=0;j<8;j++)
                    acc[i][j] += a[i]*b[j];
        }
        __syncthreads();
    }

    const float invs = rsqrtf(1.0f + BN_EPS);
    #pragma unroll
    for (int i=0;i<8;i++) {
        int gm = m0 + ty*8 + i;
        if (gm >= M) continue;
        float bi = bias  ? bias[gm]       : 0.f;
        float ga = gamma ? gamma[gm]*invs : 1.f;
        float be = beta  ? beta[gm]       : 0.f;
        #pragma unroll
        for (int j=0;j<8;j++) {
            int gn = n0 + tx*8 + j;
            if (gn >= Nc) continue;
            float r = acc[i][j]*alpha + bi;
            if (gamma) r = r*ga + be;
            if (relu)  r = fmaxf(r, 0.f);
            if (resid) r += resid[(long long)gm*ldr + gn];
            Cm[(long long)gm*ldc + gn] = r;
        }
    }
}

// ---------------- small kernels ----------------------------------------------
__global__ void prep_w1_kernel(const float* __restrict__ w1,
                               float* __restrict__ w1s, float* __restrict__ w1b)
{
    int i = blockIdx.x*blockDim.x + threadIdx.x;
    if (i < CCH*CCH) {
        int o = i / CCH, c = i % CCH;
        float a  = w1[o*2*CCH + c];
        float bb = w1[o*2*CCH + CCH + c];
        w1s[i] = a + bb;
        w1b[i] = bb;
    }
}

__global__ void xx_kernel(const float* __restrict__ gram, float* __restrict__ xx)
{
    int i = blockIdx.x*blockDim.x + threadIdx.x;
    if (i < BSZ*NPT) {
        int b = i / NPT, n = i % NPT;
        xx[i] = gram[((long long)(b*NPT+n))*NPT + n];
    }
}

// 9 sequential argmax passes over neg_d row (constant term per row dropped).
__global__ void __launch_bounds__(256) topk_kernel(const float* __restrict__ gram,
                                                   const float* __restrict__ xx,
                                                   int* __restrict__ idx)
{
    __shared__ float sv[NPT];
    __shared__ float rv[256];
    __shared__ int   ri[256];
    int n = blockIdx.x, b = blockIdx.y;
    const float* row = gram + ((long long)(b*NPT+n))*NPT;
    const float* xb  = xx + b*NPT;
    int tid = threadIdx.x;
    for (int m = tid; m < NPT; m += 256)
        sv[m] = 2.f*row[m] - xb[m];
    __syncthreads();
    for (int t = 0; t < KNNK; t++) {
        float bv = -INFINITY; int bi = 0;
        for (int m = tid; m < NPT; m += 256) {
            float v = sv[m];
            if (v > bv) { bv = v; bi = m; }
        }
        rv[tid] = bv; ri[tid] = bi;
        __syncthreads();
        for (int s = 128; s > 0; s >>= 1) {
            if (tid < s) {
                if (rv[tid+s] > rv[tid] ||
                    (rv[tid+s] == rv[tid] && ri[tid+s] < ri[tid])) {
                    rv[tid] = rv[tid+s]; ri[tid] = ri[tid+s];
                }
            }
            __syncthreads();
        }
        if (tid == 0) {
            idx[(b*NPT+n)*KNNK + t] = ri[0];
            sv[ri[0]] = -INFINITY;
        }
        __syncthreads();
    }
}

// h[b,c,n*9+k] = relu( bn( u[b,c,n] - v[b,c,idx] + b1[c] ) )
__global__ void gather_h_kernel(const float* __restrict__ u, const float* __restrict__ v,
                                const int* __restrict__ idx,
                                const float* __restrict__ b1, const float* __restrict__ g1,
                                const float* __restrict__ be1, float* __restrict__ h)
{
    long long i = (long long)blockIdx.x*blockDim.x + threadIdx.x;
    const long long total = (long long)BSZ*CCH*NPT*KNNK;
    if (i >= total) return;
    int k = (int)(i % KNNK);
    long long r = i / KNNK;
    int n = (int)(r % NPT); r /= NPT;
    int c = (int)(r % CCH);
    int b = (int)(r / CCH);
    int j = idx[(b*NPT+n)*KNNK + k];
    float uv = u[((long long)(b*CCH+c))*NPT + n];
    float vg = v[((long long)(b*CCH+c))*NPT + j];
    const float invs = rsqrtf(1.f + BN_EPS);
    float val = (uv - vg + b1[c]) * (g1[c]*invs) + be1[c];
    h[((long long)(b*CCH+c))*NPT*KNNK + (long long)n*KNNK + k] = fmaxf(val, 0.f);
}

// agg[b,c,n] = max_k h2[b,c,n*9+k]; also writes top half of cat buffer
__global__ void maxk_kernel(const float* __restrict__ h2,
                            float* __restrict__ agg, float* __restrict__ cat)
{
    int i = blockIdx.x*blockDim.x + threadIdx.x;
    if (i >= BSZ*CCH*NPT) return;
    int n = i % NPT;
    int c = (i / NPT) % CCH;
    int b = i / (NPT*CCH);
    const float* p = h2 + ((long long)(b*CCH+c))*NPT*KNNK + (long long)n*KNNK;
    float m = p[0];
    #pragma unroll
    for (int k = 1; k < KNNK; k++) m = fmaxf(m, p[k]);
    agg[i] = m;
    cat[(long long)b*2*CCH*NPT + (long long)c*NPT + n] = m;
}

__global__ void __launch_bounds__(256) softmax_kernel(float* __restrict__ scores)
{
    __shared__ float sv[NPT];
    __shared__ float red[256];
    long long row = blockIdx.x;                 // B*H*N rows
    float* p = scores + row*NPT;
    int tid = threadIdx.x;
    float mx = -INFINITY;
    for (int m = tid; m < NPT; m += 256) { float v = p[m]; sv[m] = v; mx = fmaxf(mx, v); }
    red[tid] = mx; __syncthreads();
    for (int s = 128; s > 0; s >>= 1) { if (tid < s) red[tid] = fmaxf(red[tid], red[tid+s]); __syncthreads(); }
    mx = red[0];
    __syncthreads();
    float sum = 0.f;
    for (int m = tid; m < NPT; m += 256) { float e = expf(sv[m]-mx); sv[m] = e; sum += e; }
    red[tid] = sum; __syncthreads();
    for (int s = 128; s > 0; s >>= 1) { if (tid < s) red[tid] += red[tid+s]; __syncthreads(); }
    float inv = 1.f / red[0];
    for (int m = tid; m < NPT; m += 256) p[m] = sv[m]*inv;
}

// ---------------- launch -----------------------------------------------------
static inline dim3 ggrid(int M, int Nc, int batches) {
    return dim3((Nc + TN - 1)/TN, (M + TM - 1)/TM, batches);
}

extern "C" void kernel_launch(void* const* d_in, const int* in_sizes, int n_in,
                              void* d_out, int out_size)
{
    const float* x    = (const float*)d_in[0];   // (B,C,N,1) == (B,C,N)
    const float* y    = (const float*)d_in[1];   // (B,C,N)
    const float* dgw1 = (const float*)d_in[2];
    const float* dgb1 = (const float*)d_in[3];
    const float* dgg1 = (const float*)d_in[4];
    const float* dgbe1= (const float*)d_in[5];
    const float* dgw2 = (const float*)d_in[6];
    const float* dgb2 = (const float*)d_in[7];
    const float* dgg2 = (const float*)d_in[8];
    const float* dgbe2= (const float*)d_in[9];
    const float* wq   = (const float*)d_in[10];
    const float* bq   = (const float*)d_in[11];
    const float* wk   = (const float*)d_in[12];
    const float* bk   = (const float*)d_in[13];
    const float* wv   = (const float*)d_in[14];
    const float* bv   = (const float*)d_in[15];
    const float* wmh  = (const float*)d_in[16];
    const float* bmh  = (const float*)d_in[17];
    const float* wc1  = (const float*)d_in[18];
    const float* bc1  = (const float*)d_in[19];
    const float* cg   = (const float*)d_in[20];
    const float* cbe  = (const float*)d_in[21];
    const float* wc2  = (const float*)d_in[22];
    const float* bc2  = (const float*)d_in[23];
    float* out = (float*)d_out;

    float *w1s,*w1b,*scores,*xx,*u,*v,*h,*h2,*agg,*q,*k,*vv,*add,*cat,*hc;
    int* idx;
    cudaGetSymbolAddress((void**)&w1s,    g_w1s);
    cudaGetSymbolAddress((void**)&w1b,    g_w1b);
    cudaGetSymbolAddress((void**)&scores, g_scores);
    cudaGetSymbolAddress((void**)&xx,     g_xx);
    cudaGetSymbolAddress((void**)&idx,    g_idx);
    cudaGetSymbolAddress((void**)&u,      g_u);
    cudaGetSymbolAddress((void**)&v,      g_v);
    cudaGetSymbolAddress((void**)&h,      g_h);
    cudaGetSymbolAddress((void**)&h2,     g_h2);
    cudaGetSymbolAddress((void**)&agg,    g_agg);
    cudaGetSymbolAddress((void**)&q,      g_q);
    cudaGetSymbolAddress((void**)&k,      g_k);
    cudaGetSymbolAddress((void**)&vv,     g_vv);
    cudaGetSymbolAddress((void**)&add,    g_add);
    cudaGetSymbolAddress((void**)&cat,    g_cat);
    cudaGetSymbolAddress((void**)&hc,     g_hc);

    const long long CN  = (long long)CCH*NPT;       // 256000
    const long long NN  = (long long)NPT*NPT;       // 4,000,000
    const long long CNK = (long long)CCH*NPT*KNNK;  // 2,304,000

    // 1) split/fold w1
    prep_w1_kernel<<<(CCH*CCH+255)/256, 256>>>(dgw1, w1s, w1b);

    // 2) Gram: gram[b] = x^T x   (TN, M=N=2000, K=128)
    gemm_k<true,false><<<ggrid(NPT,NPT,BSZ), 256>>>(
        x, x, scores, NPT, NPT, CCH, NPT, NPT, NPT,
        CN, CN, NN, 1.f, nullptr, nullptr, nullptr, 0, nullptr, 0, 0);

    // 3) diagonal, 4) top-9
    xx_kernel<<<(BSZ*NPT+255)/256, 256>>>(scores, xx);
    topk_kernel<<<dim3(NPT, BSZ), 256>>>(scores, xx, idx);

    // 5) u = (W1a+W1b) @ x ; 6) v = W1b @ x
    gemm_k<false,false><<<ggrid(CCH,NPT,BSZ), 256>>>(
        w1s, x, u, CCH, NPT, CCH, CCH, NPT, NPT,
        0, CN, CN, 1.f, nullptr, nullptr, nullptr, 0, nullptr, 0, 0);
    gemm_k<false,false><<<ggrid(CCH,NPT,BSZ), 256>>>(
        w1b, x, v, CCH, NPT, CCH, CCH, NPT, NPT,
        0, CN, CN, 1.f, nullptr, nullptr, nullptr, 0, nullptr, 0, 0);

    // 7) edge features -> h (with bias+bn+relu)
    {
        long long total = (long long)BSZ*CNK;
        gather_h_kernel<<<(unsigned)((total+255)/256), 256>>>(u, v, idx, dgb1, dgg1, dgbe1, h);
    }

    // 8) conv2 over 18000 cols, fused bn+relu
    gemm_k<false,false><<<ggrid(CCH, NPT*KNNK, BSZ), 256>>>(
        dgw2, h, h2, CCH, NPT*KNNK, CCH, CCH, NPT*KNNK, NPT*KNNK,
        0, CNK, CNK, 1.f, dgb2, dgg2, dgbe2, 1, nullptr, 0, 0);

    // 9) max over k -> agg (+ top half of cat)
    maxk_kernel<<<(BSZ*CCH*NPT+255)/256, 256>>>(h2, agg, cat);

    // 10) q,k,v projections
    gemm_k<false,false><<<ggrid(CCH,NPT,BSZ), 256>>>(
        wq, agg, q, CCH, NPT, CCH, CCH, NPT, NPT,
        0, CN, CN, 1.f, bq, nullptr, nullptr, 0, nullptr, 0, 0);
    gemm_k<false,false><<<ggrid(CCH,NPT,BSZ), 256>>>(
        wk, y, k, CCH, NPT, CCH, CCH, NPT, NPT,
        0, CN, CN, 1.f, bk, nullptr, nullptr, 0, nullptr, 0, 0);
    gemm_k<false,false><<<ggrid(CCH,NPT,BSZ), 256>>>(
        wv, y, vv, CCH, NPT, CCH, CCH, NPT, NPT,
        0, CN, CN, 1.f, bv, nullptr, nullptr, 0, nullptr, 0, 0);

    // 11) scores[b,h] = (q_h^T k_h)/sqrt(hd)  — 16 batched head slices
    gemm_k<true,false><<<ggrid(NPT,NPT,BSZ*NHEAD), 256>>>(
        q, k, scores, NPT, NPT, HD, NPT, NPT, NPT,
        (long long)HD*NPT, (long long)HD*NPT, NN,
        rsqrtf((float)HD), nullptr, nullptr, nullptr, 0, nullptr, 0, 0);

    // 12) row softmax
    softmax_kernel<<<BSZ*NHEAD*NPT, 256>>>(scores);

    // 13) add[b,h] = v_h @ scores^T  (NT, M=32, N=2000, K=2000)
    gemm_k<false,true><<<ggrid(HD,NPT,BSZ*NHEAD), 256>>>(
        vv, scores, add, HD, NPT, NPT, NPT, NPT, NPT,
        (long long)HD*NPT, NN, (long long)HD*NPT,
        1.f, nullptr, nullptr, nullptr, 0, nullptr, 0, 0);

    // 14) mh conv -> bottom half of cat buffer
    gemm_k<false,false><<<ggrid(CCH,NPT,BSZ), 256>>>(
        wmh, add, cat + CN, CCH, NPT, CCH, CCH, NPT, NPT,
        0, CN, 2*CN, 1.f, bmh, nullptr, nullptr, 0, nullptr, 0, 0);

    // 15) hc = relu(bn(wc1 @ cat + bc1))   (256 x 2000, K=256)
    gemm_k<false,false><<<ggrid(2*CCH,NPT,BSZ), 256>>>(
        wc1, cat, hc, 2*CCH, NPT, 2*CCH, 2*CCH, NPT, NPT,
        0, 2*CN, 2*CN, 1.f, bc1, cg, cbe, 1, nullptr, 0, 0);

    // 16) out = agg + wc2 @ hc + bc2
    gemm_k<false,false><<<ggrid(CCH,NPT,BSZ), 256>>>(
        wc2, hc, out, CCH, NPT, 2*CCH, 2*CCH, NPT, NPT,
        0, 2*CN, CN, 1.f, bc2, nullptr, nullptr, 0, agg, CN, NPT);
}

// round 2
// speedup vs baseline: 1.7601x; 1.7601x over previous
#include <cuda_runtime.h>
#include <math.h>

// Problem constants
#define BSZ   4
#define CCH   128
#define NPT   2000
#define KNNK  9
#define NHEAD 4
#define HD    32
#define BN_EPS 1e-5f

// ---------------- scratch (device globals; no allocation allowed) ------------
__device__ float g_w1sb[2*CCH*CCH];                 // [w1a+w1b ; w1b] stacked (256x128)
__device__ float g_wkv [2*CCH*CCH];                 // [wk ; wv] stacked (256x128)
__device__ float g_bkv [2*CCH];
__device__ float g_gram[(size_t)BSZ*NPT*NPT];       // 64MB
__device__ float g_xx[BSZ*NPT];
__device__ int   g_idx[BSZ*NPT*KNNK];
__device__ float g_uv[BSZ*2*CCH*NPT];               // u rows 0..127, v rows 128..255
__device__ float g_h [(size_t)BSZ*CCH*NPT*KNNK];
__device__ float g_h2[(size_t)BSZ*CCH*NPT*KNNK];
__device__ float g_agg[BSZ*CCH*NPT];
__device__ float g_q[BSZ*CCH*NPT];
__device__ float g_kv[BSZ*2*CCH*NPT];               // k rows 0..127, v rows 128..255
__device__ float g_add[BSZ*CCH*NPT];
__device__ float g_cat[BSZ*2*CCH*NPT];
__device__ float g_hc [BSZ*2*CCH*NPT];

// ---------------- generic tiled SGEMM ---------------------------------------
#define TM 128
#define TN 128
#define TK 8

template<bool TA, bool TB>
__global__ void __launch_bounds__(256) gemm_k(
    const float* __restrict__ A, const float* __restrict__ B, float* __restrict__ Cm,
    int M, int Nc, int Kc, int lda, int ldb, int ldc,
    long long sA, long long sB, long long sC,
    float alpha,
    const float* __restrict__ bias,
    const float* __restrict__ gamma, const float* __restrict__ beta,
    int relu,
    const float* __restrict__ resid, long long sR, int ldr)
{
    int bz = blockIdx.z;
    A  += (long long)bz * sA;
    B  += (long long)bz * sB;
    Cm += (long long)bz * sC;
    if (resid) resid += (long long)bz * sR;

    __shared__ float As[TK][TM];
    __shared__ float Bs[TK][TN];

    int m0 = blockIdx.y * TM;
    int n0 = blockIdx.x * TN;
    int tid = threadIdx.x;
    int tx = tid % 16, ty = tid / 16;

    float acc[8][8];
    #pragma unroll
    for (int i=0;i<8;i++)
        #pragma unroll
        for (int j=0;j<8;j++) acc[i][j] = 0.f;

    for (int kt = 0; kt < Kc; kt += TK) {
        #pragma unroll
        for (int e = tid; e < TM*TK; e += 256) {
            int m, k;
            if (TA) { m = e % TM; k = e / TM; }
            else    { k = e % TK; m = e / TK; }
            int gm = m0 + m, gk = kt + k;
            float val = 0.f;
            if (gm < M && gk < Kc)
                val = TA ? A[(long long)gk*lda + gm] : A[(long long)gm*lda + gk];
            As[k][m] = val;
        }
        #pragma unroll
        for (int e = tid; e < TN*TK; e += 256) {
            int n, k;
            if (TB) { k = e % TK; n = e / TK; }
            else    { n = e % TN; k = e / TN; }
            int gn = n0 + n, gk = kt + k;
            float val = 0.f;
            if (gn < Nc && gk < Kc)
                val = TB ? B[(long long)gn*ldb + gk] : B[(long long)gk*ldb + gn];
            Bs[k][n] = val;
        }
        __syncthreads();
        #pragma unroll
        for (int kk = 0; kk < TK; kk++) {
            float a[8], b[8];
            #pragma unroll
            for (int i=0;i<8;i++) a[i] = As[kk][ty*8+i];
            #pragma unroll
            for (int j=0;j<8;j++) b[j] = Bs[kk][tx*8+j];
            #pragma unroll
            for (int i=0;i<8;i++)
                #pragma unroll
                for (int j=0;j<8;j++)
                    acc[i][j] += a[i]*b[j];
        }
        __syncthreads();
    }

    const float invs = rsqrtf(1.0f + BN_EPS);
    #pragma unroll
    for (int i=0;i<8;i++) {
        int gm = m0 + ty*8 + i;
        if (gm >= M) continue;
        float bi = bias  ? bias[gm]       : 0.f;
        float ga = gamma ? gamma[gm]*invs : 1.f;
        float be = beta  ? beta[gm]       : 0.f;
        #pragma unroll
        for (int j=0;j<8;j++) {
            int gn = n0 + tx*8 + j;
            if (gn >= Nc) continue;
            float r = acc[i][j]*alpha + bi;
            if (gamma) r = r*ga + be;
            if (relu)  r = fmaxf(r, 0.f);
            if (resid) r += resid[(long long)gm*ldr + gn];
            Cm[(long long)gm*ldc + gn] = r;
        }
    }
}

// ---------------- prep: fold w1, stack wk/wv ----------------------------------
__global__ void prep_kernel(const float* __restrict__ w1,
                            const float* __restrict__ wk, const float* __restrict__ wv,
                            const float* __restrict__ bk, const float* __restrict__ bv,
                            float* __restrict__ w1sb, float* __restrict__ wkv,
                            float* __restrict__ bkv)
{
    int i = blockIdx.x*blockDim.x + threadIdx.x;
    if (i < CCH*CCH) {
        int o = i / CCH, c = i % CCH;
        float a  = w1[o*2*CCH + c];
        float bb = w1[o*2*CCH + CCH + c];
        w1sb[i] = a + bb;
        w1sb[CCH*CCH + i] = bb;
        wkv[i] = wk[i];
        wkv[CCH*CCH + i] = wv[i];
    }
    if (i < 2*CCH) bkv[i] = (i < CCH) ? bk[i] : bv[i - CCH];
}

__global__ void xx_kernel(const float* __restrict__ gram, float* __restrict__ xx)
{
    int i = blockIdx.x*blockDim.x + threadIdx.x;
    if (i < BSZ*NPT) {
        int b = i / NPT, n = i % NPT;
        xx[i] = gram[((long long)(b*NPT+n))*NPT + n];
    }
}

// ---------------- topk: register candidates + shuffle/tree argmax -------------
__global__ void __launch_bounds__(256) topk_kernel(const float* __restrict__ gram,
                                                   const float* __restrict__ xx,
                                                   int* __restrict__ idx)
{
    int n = blockIdx.x, b = blockIdx.y;
    const float* row = gram + ((long long)(b*NPT+n))*NPT;
    const float* xb  = xx + b*NPT;
    int tid = threadIdx.x;

    float v[8];
    #pragma unroll
    for (int j=0;j<8;j++) {
        int m = tid + j*256;
        v[j] = (m < NPT) ? (2.f*row[m] - xb[m]) : -INFINITY;
    }
    unsigned taken = 0;

    __shared__ float wvs[8];
    __shared__ int   wis[8];
    __shared__ int   sres;

    for (int t = 0; t < KNNK; t++) {
        float bv = -INFINITY; int bm = 0x7fffffff;
        #pragma unroll
        for (int j=0;j<8;j++) {
            bool ok = !((taken >> j) & 1u);
            if (ok && v[j] > bv) { bv = v[j]; bm = tid + j*256; }
        }
        #pragma unroll
        for (int s=16; s>0; s>>=1) {
            float ov = __shfl_xor_sync(0xffffffffu, bv, s);
            int   oi = __shfl_xor_sync(0xffffffffu, bm, s);
            if (ov > bv || (ov == bv && oi < bm)) { bv = ov; bm = oi; }
        }
        int w = tid >> 5;
        if ((tid & 31) == 0) { wvs[w] = bv; wis[w] = bm; }
        __syncthreads();
        if (tid == 0) {
            float fv = wvs[0]; int fm = wis[0];
            #pragma unroll
            for (int ww=1; ww<8; ww++)
                if (wvs[ww] > fv || (wvs[ww] == fv && wis[ww] < fm)) { fv = wvs[ww]; fm = wis[ww]; }
            idx[(b*NPT+n)*KNNK + t] = fm;
            sres = fm;
        }
        __syncthreads();
        int win = sres;
        if ((win & 255) == tid) taken |= 1u << (win >> 8);
        __syncthreads();
    }
}

// h[b,c,n*9+k] = relu( bn( u[b,c,n] - v[b,c,idx] + b1[c] ) )
__global__ void gather_h_kernel(const float* __restrict__ uv,
                                const int* __restrict__ idx,
                                const float* __restrict__ b1, const float* __restrict__ g1,
                                const float* __restrict__ be1, float* __restrict__ h)
{
    long long i = (long long)blockIdx.x*blockDim.x + threadIdx.x;
    const long long total = (long long)BSZ*CCH*NPT*KNNK;
    if (i >= total) return;
    int k = (int)(i % KNNK);
    long long r = i / KNNK;
    int n = (int)(r % NPT); r /= NPT;
    int c = (int)(r % CCH);
    int b = (int)(r / CCH);
    int j = idx[(b*NPT+n)*KNNK + k];
    const float* ub = uv + (long long)b*2*CCH*NPT + (long long)c*NPT;
    float uvv = ub[n];
    float vg  = ub[(long long)CCH*NPT + j];
    const float invs = rsqrtf(1.f + BN_EPS);
    float val = (uvv - vg + b1[c]) * (g1[c]*invs) + be1[c];
    h[((long long)(b*CCH+c))*NPT*KNNK + (long long)n*KNNK + k] = fmaxf(val, 0.f);
}

// agg[b,c,n] = max_k h2[b,c,n*9+k]; also writes top half of cat buffer
__global__ void maxk_kernel(const float* __restrict__ h2,
                            float* __restrict__ agg, float* __restrict__ cat)
{
    int i = blockIdx.x*blockDim.x + threadIdx.x;
    if (i >= BSZ*CCH*NPT) return;
    int n = i % NPT;
    int c = (i / NPT) % CCH;
    int b = i / (NPT*CCH);
    const float* p = h2 + ((long long)(b*CCH+c))*NPT*KNNK + (long long)n*KNNK;
    float m = p[0];
    #pragma unroll
    for (int k = 1; k < KNNK; k++) m = fmaxf(m, p[k]);
    agg[i] = m;
    cat[(long long)b*2*CCH*NPT + (long long)c*NPT + n] = m;
}

// ---------------- fused flash attention ---------------------------------------
// Per CTA: one (b,h), one 128-row q-tile. Iterates 64-col k-tiles with online
// softmax. add[b, h*32+d, n] = sum_m softmax(q^T k / sqrt(32))[n,m] * v[d,m]
#define QT 128
#define KT 64
#define QST_LD 132   // padded ld for Qst (16B aligned, bank offset 4)
#define VT_LD  36
#define PS_LD  68

__global__ void __launch_bounds__(256,2) flash_kernel(
    const float* __restrict__ q,   // [B][C][N]
    const float* __restrict__ kv,  // [B][2C][N]
    float* __restrict__ add)       // [B][C][N]
{
    extern __shared__ float sm[];
    float* Qst = sm;                         // [32][132]
    float* Ks  = Qst + HD*QST_LD;            // [32][64]
    float* Vt  = Ks  + HD*KT;                // [64][36]
    float* Ps  = Vt  + KT*VT_LD;             // [128][68]

    int n0 = blockIdx.x * QT;
    int h  = blockIdx.y;
    int b  = blockIdx.z;
    const float* qh = q  + ((long long)b*CCH   + h*HD)*NPT;
    const float* kh = kv + ((long long)b*2*CCH + h*HD)*NPT;
    const float* vh = kv + ((long long)b*2*CCH + CCH + h*HD)*NPT;
    float* oh = add + ((long long)b*CCH + h*HD)*NPT;

    int tid = threadIdx.x;
    for (int e = tid; e < HD*QT; e += 256) {
        int d = e >> 7, r = e & 127;
        int n = n0 + r;
        Qst[d*QST_LD + r] = (n < NPT) ? qh[d*NPT + n] : 0.f;
    }

    int ty = tid >> 4, tx = tid & 15;
    int rr = tid >> 1, part = tid & 1;

    float mrow = -INFINITY, lrow = 0.f;
    float O[HD];
    #pragma unroll
    for (int d=0; d<HD; d++) O[d] = 0.f;

    const float scale = 0.17677669529663689f; // 1/sqrt(32)
    const int ntiles = (NPT + KT - 1)/KT;

    for (int t = 0; t < ntiles; t++) {
        int m0 = t*KT;
        __syncthreads();
        #pragma unroll
        for (int e = tid; e < HD*KT; e += 256) {
            int d = e >> 6, c = e & 63;
            int m = m0 + c;
            float kvld = (m < NPT) ? kh[d*NPT + m] : 0.f;
            float vvld = (m < NPT) ? vh[d*NPT + m] : 0.f;
            Ks[d*KT + c]  = kvld;
            Vt[c*VT_LD + d] = vvld;
        }
        __syncthreads();

        // S = (Q^T K) * scale, microtile 8x4
        float acc[8][4];
        #pragma unroll
        for (int i=0;i<8;i++)
            #pragma unroll
            for (int j=0;j<4;j++) acc[i][j] = 0.f;
        #pragma unroll
        for (int kk=0; kk<HD; kk++) {
            float4 a0 = *(const float4*)&Qst[kk*QST_LD + ty*8];
            float4 a1 = *(const float4*)&Qst[kk*QST_LD + ty*8 + 4];
            float4 b4 = *(const float4*)&Ks[kk*KT + tx*4];
            float a[8] = {a0.x,a0.y,a0.z,a0.w,a1.x,a1.y,a1.z,a1.w};
            float bb[4] = {b4.x,b4.y,b4.z,b4.w};
            #pragma unroll
            for (int i=0;i<8;i++)
                #pragma unroll
                for (int j=0;j<4;j++) acc[i][j] += a[i]*bb[j];
        }
        #pragma unroll
        for (int i=0;i<8;i++)
            #pragma unroll
            for (int j=0;j<4;j++)
                Ps[(ty*8+i)*PS_LD + tx*4+j] = acc[i][j]*scale;
        __syncthreads();

        // online softmax: 2 threads per row, 32 cols each
        int mvalid = NPT - m0;   // valid cols this tile (>= KT except last)
        float sv[32];
        float lm = -INFINITY;
        #pragma unroll
        for (int j=0;j<32;j++) {
            int m = part*32 + j;
            float s = Ps[rr*PS_LD + m];
            sv[j] = s;
            if (m < mvalid) lm = fmaxf(lm, s);
        }
        lm = fmaxf(lm, __shfl_xor_sync(0xffffffffu, lm, 1));
        float mnew = fmaxf(mrow, lm);
        float alpha = __expf(mrow - mnew);
        mrow = mnew;
        float ls = 0.f;
        #pragma unroll
        for (int j=0;j<32;j++) {
            int m = part*32 + j;
            float e = (m < mvalid) ? __expf(sv[j] - mnew) : 0.f;
            Ps[rr*PS_LD + m] = e;
            ls += e;
        }
        lrow = lrow*alpha + ls;
        #pragma unroll
        for (int d=0;d<HD;d++) O[d] *= alpha;

        // O += P V^T over own 32 cols (stagger parts to dodge bank conflicts)
        #pragma unroll 8
        for (int ii=0; ii<32; ii++) {
            int m = ((ii + part) & 31) + part*32;
            float p = Ps[rr*PS_LD + m];
            const float* vrow = &Vt[m*VT_LD];
            #pragma unroll
            for (int d=0; d<HD; d+=4) {
                float4 v4 = *(const float4*)&vrow[d];
                O[d]   += p*v4.x;
                O[d+1] += p*v4.y;
                O[d+2] += p*v4.z;
                O[d+3] += p*v4.w;
            }
        }
    }

    // combine pair halves and write
    float lt = lrow + __shfl_xor_sync(0xffffffffu, lrow, 1);
    float inv = 1.f / lt;
    int n = n0 + rr;
    #pragma unroll
    for (int d=0; d<HD; d++) {
        float o = O[d] + __shfl_xor_sync(0xffffffffu, O[d], 1);
        int mine = (part == 0) ? (d < 16) : (d >= 16);
        if (mine && n < NPT) oh[d*NPT + n] = o*inv;
    }
}

// ---------------- launch -----------------------------------------------------
static inline dim3 ggrid(int M, int Nc, int batches) {
    return dim3((Nc + TN - 1)/TN, (M + TM - 1)/TM, batches);
}

extern "C" void kernel_launch(void* const* d_in, const int* in_sizes, int n_in,
                              void* d_out, int out_size)
{
    const float* x    = (const float*)d_in[0];
    const float* y    = (const float*)d_in[1];
    const float* dgw1 = (const float*)d_in[2];
    const float* dgb1 = (const float*)d_in[3];
    const float* dgg1 = (const float*)d_in[4];
    const float* dgbe1= (const float*)d_in[5];
    const float* dgw2 = (const float*)d_in[6];
    const float* dgb2 = (const float*)d_in[7];
    const float* dgg2 = (const float*)d_in[8];
    const float* dgbe2= (const float*)d_in[9];
    const float* wq   = (const float*)d_in[10];
    const float* bq   = (const float*)d_in[11];
    const float* wk   = (const float*)d_in[12];
    const float* bk   = (const float*)d_in[13];
    const float* wv   = (const float*)d_in[14];
    const float* bv   = (const float*)d_in[15];
    const float* wmh  = (const float*)d_in[16];
    const float* bmh  = (const float*)d_in[17];
    const float* wc1  = (const float*)d_in[18];
    const float* bc1  = (const float*)d_in[19];
    const float* cg   = (const float*)d_in[20];
    const float* cbe  = (const float*)d_in[21];
    const float* wc2  = (const float*)d_in[22];
    const float* bc2  = (const float*)d_in[23];
    float* out = (float*)d_out;

    float *w1sb,*wkv,*bkv,*gram,*xx,*uv,*h,*h2,*agg,*q,*kvb,*add,*cat,*hc;
    int* idx;
    cudaGetSymbolAddress((void**)&w1sb, g_w1sb);
    cudaGetSymbolAddress((void**)&wkv,  g_wkv);
    cudaGetSymbolAddress((void**)&bkv,  g_bkv);
    cudaGetSymbolAddress((void**)&gram, g_gram);
    cudaGetSymbolAddress((void**)&xx,   g_xx);
    cudaGetSymbolAddress((void**)&idx,  g_idx);
    cudaGetSymbolAddress((void**)&uv,   g_uv);
    cudaGetSymbolAddress((void**)&h,    g_h);
    cudaGetSymbolAddress((void**)&h2,   g_h2);
    cudaGetSymbolAddress((void**)&agg,  g_agg);
    cudaGetSymbolAddress((void**)&q,    g_q);
    cudaGetSymbolAddress((void**)&kvb,  g_kv);
    cudaGetSymbolAddress((void**)&add,  g_add);
    cudaGetSymbolAddress((void**)&cat,  g_cat);
    cudaGetSymbolAddress((void**)&hc,   g_hc);

    const long long CN  = (long long)CCH*NPT;
    const long long NN  = (long long)NPT*NPT;
    const long long CNK = (long long)CCH*NPT*KNNK;
    const int FLASH_SMEM = (HD*QST_LD + HD*KT + KT*VT_LD + QT*PS_LD) * 4;

    cudaFuncSetAttribute(flash_kernel, cudaFuncAttributeMaxDynamicSharedMemorySize, FLASH_SMEM);

    // 1) prep: fold w1 -> [w1a+w1b; w1b], stack [wk;wv], [bk;bv]
    prep_kernel<<<(CCH*CCH+255)/256, 256>>>(dgw1, wk, wv, bk, bv, w1sb, wkv, bkv);

    // 2) gram[b] = x^T x
    gemm_k<true,false><<<ggrid(NPT,NPT,BSZ), 256>>>(
        x, x, gram, NPT, NPT, CCH, NPT, NPT, NPT,
        CN, CN, NN, 1.f, nullptr, nullptr, nullptr, 0, nullptr, 0, 0);

    // 3) diag + top-9
    xx_kernel<<<(BSZ*NPT+255)/256, 256>>>(gram, xx);
    topk_kernel<<<dim3(NPT, BSZ), 256>>>(gram, xx, idx);

    // 4) uv = [w1s; w1b] @ x   (M=256)
    gemm_k<false,false><<<ggrid(2*CCH,NPT,BSZ), 256>>>(
        w1sb, x, uv, 2*CCH, NPT, CCH, CCH, NPT, NPT,
        0, CN, 2*CN, 1.f, nullptr, nullptr, nullptr, 0, nullptr, 0, 0);

    // 5) edge features -> h (bias+bn+relu fused)
    {
        long long total = (long long)BSZ*CNK;
        gather_h_kernel<<<(unsigned)((total+255)/256), 256>>>(uv, idx, dgb1, dgg1, dgbe1, h);
    }

    // 6) conv2 over 18000 cols, fused bn+relu
    gemm_k<false,false><<<ggrid(CCH, NPT*KNNK, BSZ), 256>>>(
        dgw2, h, h2, CCH, NPT*KNNK, CCH, CCH, NPT*KNNK, NPT*KNNK,
        0, CNK, CNK, 1.f, dgb2, dgg2, dgbe2, 1, nullptr, 0, 0);

    // 7) max over k -> agg (+ top half of cat)
    maxk_kernel<<<(BSZ*CCH*NPT+255)/256, 256>>>(h2, agg, cat);

    // 8) q = wq@agg ; kv = [wk;wv]@y
    gemm_k<false,false><<<ggrid(CCH,NPT,BSZ), 256>>>(
        wq, agg, q, CCH, NPT, CCH, CCH, NPT, NPT,
        0, CN, CN, 1.f, bq, nullptr, nullptr, 0, nullptr, 0, 0);
    gemm_k<false,false><<<ggrid(2*CCH,NPT,BSZ), 256>>>(
        wkv, y, kvb, 2*CCH, NPT, CCH, CCH, NPT, NPT,
        0, CN, 2*CN, 1.f, bkv, nullptr, nullptr, 0, nullptr, 0, 0);

    // 9) fused attention -> add
    {
        dim3 grid((NPT + QT - 1)/QT, NHEAD, BSZ);
        flash_kernel<<<grid, 256, FLASH_SMEM>>>(q, kvb, add);
    }

    // 10) mh conv -> bottom half of cat
    gemm_k<false,false><<<ggrid(CCH,NPT,BSZ), 256>>>(
        wmh, add, cat + CN, CCH, NPT, CCH, CCH, NPT, NPT,
        0, CN, 2*CN, 1.f, bmh, nullptr, nullptr, 0, nullptr, 0, 0);

    // 11) hc = relu(bn(wc1 @ cat + bc1))
    gemm_k<false,false><<<ggrid(2*CCH,NPT,BSZ), 256>>>(
        wc1, cat, hc, 2*CCH, NPT, 2*CCH, 2*CCH, NPT, NPT,
        0, 2*CN, 2*CN, 1.f, bc1, cg, cbe, 1, nullptr, 0, 0);

    // 12) out = agg + wc2 @ hc + bc2
    gemm_k<false,false><<<ggrid(CCH,NPT,BSZ), 256>>>(
        wc2, hc, out, CCH, NPT, 2*CCH, 2*CCH, NPT, NPT,
        0, 2*CN, CN, 1.f, bc2, nullptr, nullptr, 0, agg, CN, NPT);
}